// round 7
// baseline (speedup 1.0000x reference)
#include <cuda_runtime.h>
#include <cuda_bf16.h>
#include <cstdint>
#include <math.h>

static constexpr int DIM = 2048;
static constexpr int LD = 2048;
static constexpr float NSC_A = 3.4445f;
static constexpr float NSC_B = -4.7750f;
static constexpr float NSC_C = 2.0315f;

// ---------------- scratch (allocation-free: __device__ globals) -------------
__device__ __align__(256) float g_X[DIM * DIM];
__device__ __align__(256) __nv_bfloat16 g_Xhi [2][DIM * DIM];
__device__ __align__(256) __nv_bfloat16 g_Xlo [2][DIM * DIM];
__device__ __align__(256) __nv_bfloat16 g_XThi[2][DIM * DIM];
__device__ __align__(256) __nv_bfloat16 g_XTlo[2][DIM * DIM];
__device__ __align__(256) __nv_bfloat16 g_Ghi [DIM * DIM];
__device__ __align__(256) __nv_bfloat16 g_Glo [DIM * DIM];
__device__ __align__(256) __nv_bfloat16 g_Bhi [DIM * DIM];
__device__ __align__(256) __nv_bfloat16 g_Blo [DIM * DIM];
__device__ __align__(256) __nv_bfloat16 g_xbig_hi[16384 * DIM];
__device__ __align__(256) __nv_bfloat16 g_xbig_lo[16384 * DIM];
__device__ float g_partial[256];
__device__ float g_scale;

// ---------------- helpers ----------------------------------------------------
__device__ __forceinline__ uint32_t smem_u32(const void* p) {
    uint32_t a;
    asm("{ .reg .u64 t; cvta.to.shared.u64 t, %1; cvt.u32.u64 %0, t; }" : "=r"(a) : "l"(p));
    return a;
}
__device__ __forceinline__ void cpa16(uint32_t dst, const void* src) {
    asm volatile("cp.async.cg.shared.global [%0], [%1], 16;" :: "r"(dst), "l"(src) : "memory");
}
#define CP_COMMIT() asm volatile("cp.async.commit_group;" ::: "memory")
#define CP_WAIT1()  asm volatile("cp.async.wait_group 1;" ::: "memory")
#define CP_WAIT0()  asm volatile("cp.async.wait_group 0;" ::: "memory")

#define LDMX4(r, a)                                                              \
    asm volatile("ldmatrix.sync.aligned.m8n8.x4.shared.b16 {%0,%1,%2,%3}, [%4];" \
        : "=r"((r)[0]), "=r"((r)[1]), "=r"((r)[2]), "=r"((r)[3]) : "r"(a))

#define MMA16816(acc, a, b0, b1)                                                  \
    asm volatile("mma.sync.aligned.m16n8k16.row.col.f32.bf16.bf16.f32 "           \
        "{%0,%1,%2,%3}, {%4,%5,%6,%7}, {%8,%9}, {%0,%1,%2,%3};"                   \
        : "+f"((acc)[0]), "+f"((acc)[1]), "+f"((acc)[2]), "+f"((acc)[3])          \
        : "r"((a)[0]), "r"((a)[1]), "r"((a)[2]), "r"((a)[3]), "r"(b0), "r"(b1))

__device__ __forceinline__ void store_split4(__nv_bfloat16* H, __nv_bfloat16* L, size_t off,
                                             float f0, float f1, float f2, float f3) {
    __nv_bfloat16 h0 = __float2bfloat16(f0), h1 = __float2bfloat16(f1);
    __nv_bfloat16 h2 = __float2bfloat16(f2), h3 = __float2bfloat16(f3);
    __nv_bfloat162 hA, hB, lA, lB;
    hA.x = h0; hA.y = h1; hB.x = h2; hB.y = h3;
    lA.x = __float2bfloat16(f0 - __bfloat162float(h0));
    lA.y = __float2bfloat16(f1 - __bfloat162float(h1));
    lB.x = __float2bfloat16(f2 - __bfloat162float(h2));
    lB.y = __float2bfloat16(f3 - __bfloat162float(h3));
    *(__nv_bfloat162*)(H + off) = hA;
    *(__nv_bfloat162*)(H + off + 2) = hB;
    *(__nv_bfloat162*)(L + off) = lA;
    *(__nv_bfloat162*)(L + off + 2) = lB;
}
__device__ __forceinline__ void store_split2(__nv_bfloat16* H, __nv_bfloat16* L, size_t off,
                                             float f0, float f1) {
    __nv_bfloat16 h0 = __float2bfloat16(f0), h1 = __float2bfloat16(f1);
    __nv_bfloat162 h2, l2;
    h2.x = h0; h2.y = h1;
    l2.x = __float2bfloat16(f0 - __bfloat162float(h0));
    l2.y = __float2bfloat16(f1 - __bfloat162float(h1));
    *(__nv_bfloat162*)(H + off) = h2;
    *(__nv_bfloat162*)(L + off) = l2;
}

// ---------------- small kernels ---------------------------------------------
__global__ void norm_partial_kernel(const float* __restrict__ w, int n) {
    __shared__ float sd[256];
    float s = 0.f;
    for (int i = blockIdx.x * blockDim.x + threadIdx.x; i < n; i += gridDim.x * blockDim.x) {
        float v = w[i];
        s = fmaf(v, v, s);
    }
    sd[threadIdx.x] = s;
    __syncthreads();
    for (int o = 128; o; o >>= 1) {
        if (threadIdx.x < o) sd[threadIdx.x] += sd[threadIdx.x + o];
        __syncthreads();
    }
    if (threadIdx.x == 0) g_partial[blockIdx.x] = sd[0];
}
__global__ void norm_finalize_kernel() {
    __shared__ float sd[256];
    sd[threadIdx.x] = g_partial[threadIdx.x];
    __syncthreads();
    for (int o = 128; o; o >>= 1) {
        if (threadIdx.x < o) sd[threadIdx.x] += sd[threadIdx.x + o];
        __syncthreads();
    }
    if (threadIdx.x == 0) g_scale = 1.0f / (sqrtf(sd[0]) + 1e-7f);
}
__global__ void scale_split_kernel(const float* __restrict__ w, float* __restrict__ X,
                                   __nv_bfloat16* __restrict__ hi, __nv_bfloat16* __restrict__ lo,
                                   int n) {
    const float s = g_scale;
    for (int i = blockIdx.x * blockDim.x + threadIdx.x; i < n; i += gridDim.x * blockDim.x) {
        float v = w[i] * s;
        X[i] = v;
        __nv_bfloat16 h = __float2bfloat16(v);
        hi[i] = h;
        lo[i] = __float2bfloat16(v - __bfloat162float(h));
    }
}
__global__ void split_kernel(const float* __restrict__ s, __nv_bfloat16* __restrict__ hi,
                             __nv_bfloat16* __restrict__ lo, int n) {
    for (int i = blockIdx.x * blockDim.x + threadIdx.x; i < n; i += gridDim.x * blockDim.x) {
        float v = s[i];
        __nv_bfloat16 h = __float2bfloat16(v);
        hi[i] = h;
        lo[i] = __float2bfloat16(v - __bfloat162float(h));
    }
}
__global__ void strans_kernel(const float* __restrict__ src,
                              __nv_bfloat16* __restrict__ dhi, __nv_bfloat16* __restrict__ dlo) {
    __shared__ float t[32][33];
    int x = blockIdx.x * 32 + threadIdx.x;
    int y0 = blockIdx.y * 32;
    for (int j = threadIdx.y; j < 32; j += 8)
        t[j][threadIdx.x] = src[(size_t)(y0 + j) * LD + x];
    __syncthreads();
    int ox = blockIdx.y * 32 + threadIdx.x;
    for (int j = threadIdx.y; j < 32; j += 8) {
        float v = t[threadIdx.x][j];
        size_t o = (size_t)(blockIdx.x * 32 + j) * LD + ox;
        __nv_bfloat16 h = __float2bfloat16(v);
        dhi[o] = h;
        dlo[o] = __float2bfloat16(v - __bfloat162float(h));
    }
}

// ============ TRIANGULAR kernel v2 (modes 0/1): 4 warps, warp tile 64x64 =====
// MODE 0: v = acc                       MODE 1: v = NSC_C*acc + NSC_B*aux(hi+lo)
// Writes split C tile + mirrored tile (symmetric output).
static constexpr int BTK = 32;
static constexpr int NCT = DIM / BTK;          // 64 chunks
static constexpr int TPITCH = 80;              // 64B data + 16B pad
static constexpr int AT_B = 128 * TPITCH;      // 10240
static constexpr int STG_T = 4 * AT_B;         // 40960
static constexpr int NSTG_T = 3;
static constexpr int SMEM_TRI = NSTG_T * STG_T;  // 122880

template <int MODE>
__global__ __launch_bounds__(128, 1) void mmagemm_tri(
    const __nv_bfloat16* __restrict__ Ahi, const __nv_bfloat16* __restrict__ Alo,
    const __nv_bfloat16* __restrict__ Bhi, const __nv_bfloat16* __restrict__ Blo,
    const __nv_bfloat16* __restrict__ auxhi, const __nv_bfloat16* __restrict__ auxlo,
    __nv_bfloat16* __restrict__ Chi, __nv_bfloat16* __restrict__ Clo) {
    extern __shared__ char sm[];
    const uint32_t smb = smem_u32(sm);
    const int tid = threadIdx.x;
    const int wid = tid >> 5;
    const int lane = tid & 31;

    const int i = blockIdx.x;
    float fq = sqrtf(8.0f * (float)i + 1.0f);
    int tn = (int)((fq - 1.0f) * 0.5f);
    while ((tn + 1) * (tn + 2) / 2 <= i) tn++;
    while (tn * (tn + 1) / 2 > i) tn--;
    int tm = i - tn * (tn + 1) / 2;
    const int bM = tm * 128;
    const int bN = tn * 128;

    auto load_chunk = [&](int c, int s) {
        const uint32_t st = smb + s * STG_T;
#pragma unroll
        for (int it = 0; it < 8; it++) {
            const int idx = tid + it * 128;   // 0..1023
            const int row = idx >> 2;         // 0..255
            const int q = idx & 3;
            if (row < 128) {
                const size_t g = (size_t)(bM + row) * LD + c * BTK + q * 8;
                const uint32_t so = st + row * TPITCH + q * 16;
                cpa16(so, Ahi + g);
                cpa16(so + AT_B, Alo + g);
            } else {
                const int br = row - 128;
                const size_t g = (size_t)(bN + br) * LD + c * BTK + q * 8;
                const uint32_t so = st + 2 * AT_B + br * TPITCH + q * 16;
                cpa16(so, Bhi + g);
                cpa16(so + AT_B, Blo + g);
            }
        }
    };

    // warp grid 2(m) x 2(n); warp tile 64x64
    const int wm = wid & 1;
    const int wn = wid >> 1;
    const int arowL = wm * 64 + (lane & 15);
    const int aChunk = lane >> 4;
    const int browL = wn * 64 + (lane & 7) + ((lane >> 4) & 1) * 8;
    const int bChunk = (lane >> 3) & 1;

    float acc[4][8][4];
#pragma unroll
    for (int a = 0; a < 4; a++)
#pragma unroll
        for (int b = 0; b < 8; b++)
#pragma unroll
            for (int q = 0; q < 4; q++) acc[a][b][q] = 0.f;

    load_chunk(0, 0);
    CP_COMMIT();
    load_chunk(1, 1);
    CP_COMMIT();

#pragma unroll 1
    for (int c = 0; c < NCT; c++) {
        if (c + 1 < NCT) CP_WAIT1(); else CP_WAIT0();
        __syncthreads();
        if (c + 2 < NCT) { load_chunk(c + 2, (c + 2) % NSTG_T); CP_COMMIT(); }

        const uint32_t st = smb + (c % NSTG_T) * STG_T;
#pragma unroll
        for (int kk = 0; kk < 2; kk++) {
            uint32_t ah[4][4], al[4][4];
#pragma unroll
            for (int mt = 0; mt < 4; mt++) {
                const uint32_t addr = st + (uint32_t)(arowL + mt * 16) * TPITCH +
                                      (uint32_t)(kk * 2 + aChunk) * 16;
                LDMX4(ah[mt], addr);
                LDMX4(al[mt], addr + AT_B);
            }
            uint32_t bh[4][4], bl[4][4];
#pragma unroll
            for (int nt = 0; nt < 4; nt++) {
                const uint32_t addr = st + 2 * AT_B +
                                      (uint32_t)(browL + nt * 16) * TPITCH +
                                      (uint32_t)(kk * 2 + bChunk) * 16;
                LDMX4(bh[nt], addr);
                LDMX4(bl[nt], addr + AT_B);
            }
#pragma unroll
            for (int mt = 0; mt < 4; mt++)
#pragma unroll
                for (int nt = 0; nt < 4; nt++) {
                    MMA16816(acc[mt][2 * nt],     ah[mt], bh[nt][0], bh[nt][1]);
                    MMA16816(acc[mt][2 * nt],     ah[mt], bl[nt][0], bl[nt][1]);
                    MMA16816(acc[mt][2 * nt],     al[mt], bh[nt][0], bh[nt][1]);
                    MMA16816(acc[mt][2 * nt + 1], ah[mt], bh[nt][2], bh[nt][3]);
                    MMA16816(acc[mt][2 * nt + 1], ah[mt], bl[nt][2], bl[nt][3]);
                    MMA16816(acc[mt][2 * nt + 1], al[mt], bh[nt][2], bh[nt][3]);
                }
        }
    }

    // ---- staged epilogue: 128x128 fp32 stage (64 KB), swizzle col^(row&31) --
    const int qrow = lane >> 2;
    const int qcol = (lane & 3) * 2;
    float* stage = (float*)sm;
    __syncthreads();
#pragma unroll
    for (int mt = 0; mt < 4; mt++) {
#pragma unroll
        for (int h = 0; h < 2; h++) {
            const int rl = wm * 64 + mt * 16 + qrow + h * 8;
#pragma unroll
            for (int n8 = 0; n8 < 8; n8++) {
                const int cl = wn * 64 + n8 * 8 + qcol;
                float v0 = acc[mt][n8][h * 2 + 0];
                float v1 = acc[mt][n8][h * 2 + 1];
                if (MODE == 1) {
                    const size_t ao = (size_t)(bM + rl) * LD + bN + cl;
                    __nv_bfloat162 a2 = *(const __nv_bfloat162*)(auxhi + ao);
                    __nv_bfloat162 l2 = *(const __nv_bfloat162*)(auxlo + ao);
                    v0 = NSC_C * v0 + NSC_B * (__bfloat162float(a2.x) + __bfloat162float(l2.x));
                    v1 = NSC_C * v1 + NSC_B * (__bfloat162float(a2.y) + __bfloat162float(l2.y));
                }
                stage[rl * 128 + (cl ^ (rl & 31))] = v0;
                stage[rl * 128 + ((cl + 1) ^ (rl & 31))] = v1;
            }
        }
    }
    __syncthreads();

    const int c4 = lane * 4;
    // normal orientation: warp w rows w*32..+31
#pragma unroll 4
    for (int rr = 0; rr < 32; rr++) {
        const int r = wid * 32 + rr;
        const int rx = r & 31;
        float f0 = stage[r * 128 + ((c4 + 0) ^ rx)];
        float f1 = stage[r * 128 + ((c4 + 1) ^ rx)];
        float f2 = stage[r * 128 + ((c4 + 2) ^ rx)];
        float f3 = stage[r * 128 + ((c4 + 3) ^ rx)];
        store_split4(Chi, Clo, (size_t)(bM + r) * LD + bN + c4, f0, f1, f2, f3);
    }
    if (tm != tn) {
#pragma unroll 4
        for (int rr = 0; rr < 32; rr++) {
            const int r = wid * 32 + rr;
            float f0 = stage[(c4 + 0) * 128 + (r ^ ((c4 + 0) & 31))];
            float f1 = stage[(c4 + 1) * 128 + (r ^ ((c4 + 1) & 31))];
            float f2 = stage[(c4 + 2) * 128 + (r ^ ((c4 + 2) & 31))];
            float f3 = stage[(c4 + 3) * 128 + (r ^ ((c4 + 3) & 31))];
            store_split4(Chi, Clo, (size_t)(bN + r) * LD + bM + c4, f0, f1, f2, f3);
        }
    }
}

// ============ BIG kernel (modes 2/3): CTA 128x256, warp tile 64x64 ===========
static constexpr int B2M = 128, B2N = 256, B2K = 32;
static constexpr int NC2 = DIM / B2K;                    // 64 chunks
static constexpr int PITCH = 80;
static constexpr int A2_B = B2M * PITCH;                 // 10240
static constexpr int B2_B = B2N * PITCH;                 // 20480
static constexpr int STG2 = 2 * A2_B + 2 * B2_B;         // 61440
static constexpr int NSTG2 = 3;
static constexpr int SMEM_BIG = NSTG2 * STG2;            // 184320

template <int MODE>
__global__ __launch_bounds__(256, 1) void mmagemm_big(
    const __nv_bfloat16* __restrict__ Ahi, const __nv_bfloat16* __restrict__ Alo,
    const __nv_bfloat16* __restrict__ Bhi, const __nv_bfloat16* __restrict__ Blo,
    const __nv_bfloat16* __restrict__ auxhi, const __nv_bfloat16* __restrict__ auxlo,
    const float* __restrict__ bias,
    __nv_bfloat16* __restrict__ Chi, __nv_bfloat16* __restrict__ Clo,
    __nv_bfloat16* __restrict__ Thi, __nv_bfloat16* __restrict__ Tlo,
    float* __restrict__ Cf32) {
    extern __shared__ char sm[];
    const uint32_t smb = smem_u32(sm);
    const int tid = threadIdx.x;
    const int wid = tid >> 5;
    const int lane = tid & 31;
    const int bM = blockIdx.y * B2M;
    const int bN = blockIdx.x * B2N;

    auto load_chunk = [&](int c, int s) {
        const uint32_t st = smb + s * STG2;
#pragma unroll
        for (int it = 0; it < 6; it++) {
            const int i = tid + it * 256;
            const int row = i >> 2;
            const int q = i & 3;
            if (row < B2M) {
                const size_t g = (size_t)(bM + row) * LD + c * B2K + q * 8;
                const uint32_t so = st + row * PITCH + q * 16;
                cpa16(so, Ahi + g);
                cpa16(so + A2_B, Alo + g);
            } else {
                const int br = row - B2M;
                const size_t g = (size_t)(bN + br) * LD + c * B2K + q * 8;
                const uint32_t so = st + 2 * A2_B + br * PITCH + q * 16;
                cpa16(so, Bhi + g);
                cpa16(so + B2_B, Blo + g);
            }
        }
    };

    const int wm = wid & 1;
    const int wn = wid >> 1;
    const int arowL = wm * 64 + (lane & 15);
    const int aChunk = lane >> 4;
    const int browL = wn * 64 + (lane & 7) + ((lane >> 4) & 1) * 8;
    const int bChunk = (lane >> 3) & 1;

    float acc[4][8][4];
#pragma unroll
    for (int a = 0; a < 4; a++)
#pragma unroll
        for (int b = 0; b < 8; b++)
#pragma unroll
            for (int q = 0; q < 4; q++) acc[a][b][q] = 0.f;

    load_chunk(0, 0);
    CP_COMMIT();
    load_chunk(1, 1);
    CP_COMMIT();

#pragma unroll 1
    for (int c = 0; c < NC2; c++) {
        if (c + 1 < NC2) CP_WAIT1(); else CP_WAIT0();
        __syncthreads();
        if (c + 2 < NC2) { load_chunk(c + 2, (c + 2) % NSTG2); CP_COMMIT(); }

        const uint32_t st = smb + (c % NSTG2) * STG2;
#pragma unroll
        for (int kk = 0; kk < 2; kk++) {
            uint32_t ah[4][4], al[4][4];
#pragma unroll
            for (int mt = 0; mt < 4; mt++) {
                const uint32_t addr = st + (uint32_t)(arowL + mt * 16) * PITCH +
                                      (uint32_t)(kk * 2 + aChunk) * 16;
                LDMX4(ah[mt], addr);
                LDMX4(al[mt], addr + A2_B);
            }
            uint32_t bh[4][4], bl[4][4];
#pragma unroll
            for (int nt = 0; nt < 4; nt++) {
                const uint32_t addr = st + 2 * A2_B +
                                      (uint32_t)(browL + nt * 16) * PITCH +
                                      (uint32_t)(kk * 2 + bChunk) * 16;
                LDMX4(bh[nt], addr);
                LDMX4(bl[nt], addr + B2_B);
            }
#pragma unroll
            for (int mt = 0; mt < 4; mt++)
#pragma unroll
                for (int nt = 0; nt < 4; nt++) {
                    MMA16816(acc[mt][2 * nt],     ah[mt], bh[nt][0], bh[nt][1]);
                    MMA16816(acc[mt][2 * nt],     ah[mt], bl[nt][0], bl[nt][1]);
                    MMA16816(acc[mt][2 * nt],     al[mt], bh[nt][0], bh[nt][1]);
                    MMA16816(acc[mt][2 * nt + 1], ah[mt], bh[nt][2], bh[nt][3]);
                    MMA16816(acc[mt][2 * nt + 1], ah[mt], bl[nt][2], bl[nt][3]);
                    MMA16816(acc[mt][2 * nt + 1], al[mt], bh[nt][2], bh[nt][3]);
                }
        }
    }

    const int qrow = lane >> 2;
    const int qcol = (lane & 3) * 2;

    if (MODE == 3) {
#pragma unroll
        for (int mt = 0; mt < 4; mt++) {
#pragma unroll
            for (int h = 0; h < 2; h++) {
                const int row = bM + wm * 64 + mt * 16 + qrow + h * 8;
                float* cr = Cf32 + (size_t)row * LD;
#pragma unroll
                for (int n8 = 0; n8 < 8; n8++) {
                    const int col = bN + wn * 64 + n8 * 8 + qcol;
                    float2 b2 = *(const float2*)(bias + col);
                    float2 o;
                    o.x = acc[mt][n8][h * 2 + 0] + b2.x;
                    o.y = acc[mt][n8][h * 2 + 1] + b2.y;
                    *(float2*)(cr + col) = o;
                }
            }
        }
        return;
    }

    // MODE 2: stage 128x256 fp32 (128 KB), swizzle col ^ (row & 31)
    float* stage = (float*)sm;
    __syncthreads();
#pragma unroll
    for (int mt = 0; mt < 4; mt++) {
#pragma unroll
        for (int h = 0; h < 2; h++) {
            const int rl = wm * 64 + mt * 16 + qrow + h * 8;
#pragma unroll
            for (int n8 = 0; n8 < 8; n8++) {
                const int cl = wn * 64 + n8 * 8 + qcol;
                float v0 = acc[mt][n8][h * 2 + 0];
                float v1 = acc[mt][n8][h * 2 + 1];
                const size_t ao = (size_t)(bM + rl) * LD + bN + cl;
                __nv_bfloat162 a2 = *(const __nv_bfloat162*)(auxhi + ao);
                __nv_bfloat162 l2 = *(const __nv_bfloat162*)(auxlo + ao);
                v0 = fmaf(NSC_A, __bfloat162float(a2.x) + __bfloat162float(l2.x), v0);
                v1 = fmaf(NSC_A, __bfloat162float(a2.y) + __bfloat162float(l2.y), v1);
                stage[rl * 256 + (cl ^ (rl & 31))] = v0;
                stage[rl * 256 + ((cl + 1) ^ (rl & 31))] = v1;
            }
        }
    }
    __syncthreads();

    {
        const int cb = lane * 2;
#pragma unroll 2
        for (int rr = 0; rr < 16; rr++) {
            const int r = wid * 16 + rr;
            const int rx = r & 31;
#pragma unroll
            for (int j = 0; j < 4; j++) {
                const int c = cb + 64 * j;
                float f0 = stage[r * 256 + (c ^ rx)];
                float f1 = stage[r * 256 + ((c + 1) ^ rx)];
                store_split2(Chi, Clo, (size_t)(bM + r) * LD + bN + c, f0, f1);
            }
        }
    }
    {
        const int cb = lane * 2;
#pragma unroll 2
        for (int rr = 0; rr < 32; rr++) {
            const int rp = wid * 32 + rr;
#pragma unroll
            for (int j = 0; j < 2; j++) {
                const int cp = cb + 64 * j;
                float f0 = stage[cp * 256 + (rp ^ (cp & 31))];
                float f1 = stage[(cp + 1) * 256 + (rp ^ ((cp + 1) & 31))];
                store_split2(Thi, Tlo, (size_t)(bN + rp) * LD + bM + cp, f0, f1);
            }
        }
    }
}

// ---------------- launch -----------------------------------------------------
extern "C" void kernel_launch(void* const* d_in, const int* in_sizes, int n_in,
                              void* d_out, int out_size) {
    const float* x = nullptr;
    const float* w = nullptr;
    const float* bias = nullptr;
    int x_size = 0;
    for (int i = 0; i < n_in; i++) {
        const int sz = in_sizes[i];
        if (sz == DIM) bias = (const float*)d_in[i];
        else if (sz == DIM * DIM) w = (const float*)d_in[i];
        else { x = (const float*)d_in[i]; x_size = sz; }
    }
    const int B_rows = x_size / DIM;  // 16384
    float* out = (float*)d_out;

    float* pX;
    __nv_bfloat16 *pXhi[2], *pXlo[2], *pXThi[2], *pXTlo[2];
    __nv_bfloat16 *pGhi, *pGlo, *pBhi, *pBlo, *pxh, *pxl;
    cudaGetSymbolAddress((void**)&pX, g_X);
    {
        __nv_bfloat16* base;
        cudaGetSymbolAddress((void**)&base, g_Xhi);
        pXhi[0] = base; pXhi[1] = base + DIM * DIM;
        cudaGetSymbolAddress((void**)&base, g_Xlo);
        pXlo[0] = base; pXlo[1] = base + DIM * DIM;
        cudaGetSymbolAddress((void**)&base, g_XThi);
        pXThi[0] = base; pXThi[1] = base + DIM * DIM;
        cudaGetSymbolAddress((void**)&base, g_XTlo);
        pXTlo[0] = base; pXTlo[1] = base + DIM * DIM;
    }
    cudaGetSymbolAddress((void**)&pGhi, g_Ghi);
    cudaGetSymbolAddress((void**)&pGlo, g_Glo);
    cudaGetSymbolAddress((void**)&pBhi, g_Bhi);
    cudaGetSymbolAddress((void**)&pBlo, g_Blo);
    cudaGetSymbolAddress((void**)&pxh, g_xbig_hi);
    cudaGetSymbolAddress((void**)&pxl, g_xbig_lo);

    cudaFuncSetAttribute(mmagemm_tri<0>, cudaFuncAttributeMaxDynamicSharedMemorySize, SMEM_TRI);
    cudaFuncSetAttribute(mmagemm_tri<1>, cudaFuncAttributeMaxDynamicSharedMemorySize, SMEM_TRI);
    cudaFuncSetAttribute(mmagemm_big<2>, cudaFuncAttributeMaxDynamicSharedMemorySize, SMEM_BIG);
    cudaFuncSetAttribute(mmagemm_big<3>, cudaFuncAttributeMaxDynamicSharedMemorySize, SMEM_BIG);

    const int n = DIM * DIM;
    norm_partial_kernel<<<256, 256>>>(w, n);
    norm_finalize_kernel<<<1, 256>>>();
    scale_split_kernel<<<1024, 256>>>(w, pX, pXhi[0], pXlo[0], n);
    strans_kernel<<<dim3(64, 64), dim3(32, 8)>>>(pX, pXThi[0], pXTlo[0]);
    split_kernel<<<8192, 256>>>(x, pxh, pxl, B_rows * DIM);

    const int NT = 16;
    dim3 gtri(NT * (NT + 1) / 2, 1);         // 136 CTAs
    dim3 g2(DIM / B2N, DIM / B2M);           // (8, 16) = 128 CTAs
    for (int s = 0; s < 10; s++) {
        const int c0 = s & 1, n1 = c0 ^ 1;
        // G = X @ X^T (symmetric, triangular + mirror)
        mmagemm_tri<0><<<gtri, 128, SMEM_TRI>>>(
            pXhi[c0], pXlo[c0], pXhi[c0], pXlo[c0],
            nullptr, nullptr, pGhi, pGlo);
        // Bm = c*(G@G) + b*G (symmetric, triangular + mirror)
        mmagemm_tri<1><<<gtri, 128, SMEM_TRI>>>(
            pGhi, pGlo, pGhi, pGlo,
            pGhi, pGlo, pBhi, pBlo);
        // X' = Bm@X + a*X ; writes X'[n1] split + X'^T[n1] split
        mmagemm_big<2><<<g2, 256, SMEM_BIG>>>(
            pBhi, pBlo, pXThi[c0], pXTlo[c0],
            pXhi[c0], pXlo[c0], nullptr,
            pXhi[n1], pXlo[n1], pXThi[n1], pXTlo[n1], nullptr);
    }
    // out = x @ Xfinal + bias
    dim3 gout(DIM / B2N, B_rows / B2M);  // (8, 128)
    mmagemm_big<3><<<gout, 256, SMEM_BIG>>>(
        pxh, pxl, pXThi[0], pXTlo[0],
        nullptr, nullptr, bias, nullptr, nullptr, nullptr, nullptr, out);
}